// round 1
// baseline (speedup 1.0000x reference)
#include <cuda_runtime.h>
#include <cuda_bf16.h>

#define N_QUBITS 10
#define DIM 1024
#define IN_F 512
#define OUT_F 64
#define BATCH 4096
#define N_LAYERS 4

// Scratch: h = relu(x @ W_pre^T) [BATCH, DIM]
__device__ float g_h[BATCH * DIM];
// Precomputed Rot matrices: [L*Q][2] float4 = {U00r,U00i,U01r,U01i},{U10r,U10i,U11r,U11i}
__device__ float4 g_U[N_LAYERS * N_QUBITS][2];

// ---------------------------------------------------------------------------
// K0: build 2x2 complex Rot matrices from q_weights [L, Q, 3]
// Rot(phi,theta,omega) = RZ(omega) RY(theta) RZ(phi)
// ---------------------------------------------------------------------------
__global__ void prep_gates_kernel(const float* __restrict__ qw) {
    int t = threadIdx.x;
    if (t < N_LAYERS * N_QUBITS) {
        float phi = qw[t * 3 + 0];
        float theta = qw[t * 3 + 1];
        float omega = qw[t * 3 + 2];
        float c = cosf(0.5f * theta);
        float s = sinf(0.5f * theta);
        float apo = 0.5f * (phi + omega);
        float apm = 0.5f * (phi - omega);
        float spo, cpo, spm, cpm;
        sincosf(apo, &spo, &cpo);
        sincosf(apm, &spm, &cpm);
        // U00 = e^{-i apo} c ; U01 = -e^{+i apm} s
        g_U[t][0] = make_float4(cpo * c, -spo * c, -cpm * s, -spm * s);
        // U10 = e^{-i apm} s ; U11 = e^{+i apo} c
        g_U[t][1] = make_float4(cpm * s, -spm * s, cpo * c, spo * c);
    }
}

// ---------------------------------------------------------------------------
// K1: C[m][n] = relu(sum_k A[m][k]*B[n][k] + bias[n])
// A = x [4096, 512], B = W_pre [1024, 512], C = g_h [4096, 1024]
// 128x128x16 tiles, 256 threads, 8x8 per-thread microtile.
// ---------------------------------------------------------------------------
#define BM 128
#define BN 128
#define BK 16
#define PAD 4

__global__ __launch_bounds__(256, 2) void gemm_relu_kernel(
    const float* __restrict__ A, const float* __restrict__ B,
    const float* __restrict__ bias) {
    __shared__ float As[BK][BM + PAD];
    __shared__ float Bs[BK][BN + PAD];

    const int K = IN_F;
    const int N = DIM;
    int tid = threadIdx.x;
    int tx = tid & 15;        // 0..15
    int ty = tid >> 4;        // 0..15
    int bm = blockIdx.y * BM;
    int bn = blockIdx.x * BN;

    int lrow = tid >> 2;           // 0..63
    int lcol = (tid & 3) << 2;     // 0,4,8,12

    const float* Ap = A + (size_t)(bm + lrow) * K + lcol;
    const float* Bp = B + (size_t)(bn + lrow) * K + lcol;

    float acc[8][8];
#pragma unroll
    for (int i = 0; i < 8; i++)
#pragma unroll
        for (int j = 0; j < 8; j++) acc[i][j] = 0.f;

    for (int k0 = 0; k0 < K; k0 += BK) {
        float4 a0 = *(const float4*)(Ap + k0);
        float4 a1 = *(const float4*)(Ap + (size_t)64 * K + k0);
        float4 b0 = *(const float4*)(Bp + k0);
        float4 b1 = *(const float4*)(Bp + (size_t)64 * K + k0);
        __syncthreads();
        As[lcol + 0][lrow] = a0.x; As[lcol + 1][lrow] = a0.y;
        As[lcol + 2][lrow] = a0.z; As[lcol + 3][lrow] = a0.w;
        As[lcol + 0][lrow + 64] = a1.x; As[lcol + 1][lrow + 64] = a1.y;
        As[lcol + 2][lrow + 64] = a1.z; As[lcol + 3][lrow + 64] = a1.w;
        Bs[lcol + 0][lrow] = b0.x; Bs[lcol + 1][lrow] = b0.y;
        Bs[lcol + 2][lrow] = b0.z; Bs[lcol + 3][lrow] = b0.w;
        Bs[lcol + 0][lrow + 64] = b1.x; Bs[lcol + 1][lrow + 64] = b1.y;
        Bs[lcol + 2][lrow + 64] = b1.z; Bs[lcol + 3][lrow + 64] = b1.w;
        __syncthreads();
#pragma unroll
        for (int kk = 0; kk < BK; kk++) {
            float ra[8], rb[8];
            *(float4*)&ra[0] = *(const float4*)&As[kk][ty * 8];
            *(float4*)&ra[4] = *(const float4*)&As[kk][ty * 8 + 4];
            *(float4*)&rb[0] = *(const float4*)&Bs[kk][tx * 8];
            *(float4*)&rb[4] = *(const float4*)&Bs[kk][tx * 8 + 4];
#pragma unroll
            for (int i = 0; i < 8; i++)
#pragma unroll
                for (int j = 0; j < 8; j++) acc[i][j] += ra[i] * rb[j];
        }
    }

    float bj[8];
#pragma unroll
    for (int j = 0; j < 8; j++) bj[j] = bias[bn + tx * 8 + j];

#pragma unroll
    for (int i = 0; i < 8; i++) {
        int row = bm + ty * 8 + i;
        float4 o0, o1;
        float v[8];
#pragma unroll
        for (int j = 0; j < 8; j++) {
            float t = acc[i][j] + bj[j];
            v[j] = t > 0.f ? t : 0.f;
        }
        o0 = make_float4(v[0], v[1], v[2], v[3]);
        o1 = make_float4(v[4], v[5], v[6], v[7]);
        *(float4*)&g_h[(size_t)row * N + bn + tx * 8] = o0;
        *(float4*)&g_h[(size_t)row * N + bn + tx * 8 + 4] = o1;
    }
}

// ---------------------------------------------------------------------------
// K2: per-row statevector simulation + expvals + post linear
// One block = one batch row. State in smem as separate re/im arrays.
// Normalization folded into the final division by ||h||^2 (circuit is unitary).
// ---------------------------------------------------------------------------
__global__ __launch_bounds__(256) void quantum_kernel(
    const float* __restrict__ W_post, const float* __restrict__ b_post,
    float* __restrict__ out) {
    __shared__ float sre[DIM];
    __shared__ float sim[DIM];
    __shared__ float red[8];          // norm^2 partials per warp
    __shared__ float zred[8][N_QUBITS];
    __shared__ float zfin[N_QUBITS];

    int b = blockIdx.x;
    int tid = threadIdx.x;
    int lane = tid & 31;
    int warp = tid >> 5;

    const float* hrow = g_h + (size_t)b * DIM;

    // Load amplitudes (real), accumulate norm^2
    float n2 = 0.f;
#pragma unroll
    for (int it = 0; it < DIM / 256; it++) {
        int i = tid + it * 256;
        float v = hrow[i];
        sre[i] = v;
        sim[i] = 0.f;
        n2 += v * v;
    }
#pragma unroll
    for (int o = 16; o; o >>= 1) n2 += __shfl_xor_sync(0xffffffffu, n2, o);
    if (lane == 0) red[warp] = n2;

    // Circuit
    for (int l = 0; l < N_LAYERS; l++) {
        // single-qubit Rot on every wire
        for (int w = 0; w < N_QUBITS; w++) {
            float4 u0 = g_U[l * N_QUBITS + w][0];
            float4 u1 = g_U[l * N_QUBITS + w][1];
            int bb = 9 - w;                  // bit position of wire w
            int lowmask = (1 << bb) - 1;
            __syncthreads();
#pragma unroll
            for (int pp = 0; pp < 2; pp++) {
                int p = tid + pp * 256;      // pair index 0..511
                int i0 = ((p >> bb) << (bb + 1)) | (p & lowmask);
                int i1 = i0 | (1 << bb);
                float ar = sre[i0], ai = sim[i0];
                float br = sre[i1], bi = sim[i1];
                float n0r = u0.x * ar - u0.y * ai + u0.z * br - u0.w * bi;
                float n0i = u0.x * ai + u0.y * ar + u0.z * bi + u0.w * br;
                float n1r = u1.x * ar - u1.y * ai + u1.z * br - u1.w * bi;
                float n1i = u1.x * ai + u1.y * ar + u1.z * bi + u1.w * br;
                sre[i0] = n0r; sim[i0] = n0i;
                sre[i1] = n1r; sim[i1] = n1i;
            }
        }
        // CNOT ring with range r
        int r = (l % (N_QUBITS - 1)) + 1;
        for (int w = 0; w < N_QUBITS; w++) {
            int c = w;
            int t = (w + r) % N_QUBITS;
            int cb = 9 - c, tb = 9 - t;
            int b1 = cb < tb ? cb : tb;
            int b2 = cb < tb ? tb : cb;
            __syncthreads();
            // 256 swaps, exactly one per thread
            int q = tid;
            int low = q & ((1 << b1) - 1);
            int mid = (q >> b1) & ((1 << (b2 - 1 - b1)) - 1);
            int high = q >> (b2 - 1);
            int i0 = (high << (b2 + 1)) | (mid << (b1 + 1)) | low | (1 << cb);
            int i1 = i0 | (1 << tb);
            float t0r = sre[i0], t0i = sim[i0];
            float t1r = sre[i1], t1i = sim[i1];
            sre[i0] = t1r; sim[i0] = t1i;
            sre[i1] = t0r; sim[i1] = t0i;
        }
    }

    __syncthreads();

    // PauliZ expvals (unnormalized; divide by norm^2 at the end)
    float zl[N_QUBITS];
#pragma unroll
    for (int i = 0; i < N_QUBITS; i++) zl[i] = 0.f;
#pragma unroll
    for (int e = 0; e < 4; e++) {
        int s = tid * 4 + e;
        float p = sre[s] * sre[s] + sim[s] * sim[s];
#pragma unroll
        for (int i = 0; i < N_QUBITS; i++)
            zl[i] += ((s >> (9 - i)) & 1) ? -p : p;
    }
#pragma unroll
    for (int i = 0; i < N_QUBITS; i++) {
#pragma unroll
        for (int o = 16; o; o >>= 1)
            zl[i] += __shfl_xor_sync(0xffffffffu, zl[i], o);
    }
    if (lane == 0) {
#pragma unroll
        for (int i = 0; i < N_QUBITS; i++) zred[warp][i] = zl[i];
    }
    __syncthreads();

    if (tid < N_QUBITS) {
        float norm2 = 0.f;
#pragma unroll
        for (int w = 0; w < 8; w++) norm2 += red[w];
        float s = 0.f;
#pragma unroll
        for (int w = 0; w < 8; w++) s += zred[w][tid];
        zfin[tid] = s / norm2;
    }
    __syncthreads();

    // Post linear: out[b][o] = b_post[o] + sum_i z[i] * W_post[o][i]
    if (tid < OUT_F) {
        float acc = b_post[tid];
#pragma unroll
        for (int i = 0; i < N_QUBITS; i++)
            acc += zfin[i] * W_post[tid * N_QUBITS + i];
        out[(size_t)b * OUT_F + tid] = acc;
    }
}

// ---------------------------------------------------------------------------
extern "C" void kernel_launch(void* const* d_in, const int* in_sizes, int n_in,
                              void* d_out, int out_size) {
    const float* x      = (const float*)d_in[0];
    const float* W_pre  = (const float*)d_in[1];
    const float* b_pre  = (const float*)d_in[2];
    const float* qw     = (const float*)d_in[3];
    const float* W_post = (const float*)d_in[4];
    const float* b_post = (const float*)d_in[5];
    float* out = (float*)d_out;

    prep_gates_kernel<<<1, 64>>>(qw);

    dim3 g1(DIM / BN, BATCH / BM);
    gemm_relu_kernel<<<g1, 256>>>(x, W_pre, b_pre);

    quantum_kernel<<<BATCH, 256>>>(W_post, b_post, out);
}

// round 2
// speedup vs baseline: 1.0718x; 1.0718x over previous
#include <cuda_runtime.h>
#include <cuda_bf16.h>
#include <cstdint>

#define N_QUBITS 10
#define DIM 1024
#define IN_F 512
#define OUT_F 64
#define BATCH 4096
#define N_LAYERS 4

// Scratch: h = relu(x @ W_pre^T) [BATCH, DIM]
__device__ float g_h[BATCH * DIM];
// Precomputed Rot matrices: [L*Q][2] float4 = {U00r,U00i,U01r,U01i},{U10r,U10i,U11r,U11i}
__device__ float4 g_U[N_LAYERS * N_QUBITS][2];

// ---------------------------------------------------------------------------
// K0: build 2x2 complex Rot matrices from q_weights [L, Q, 3]
// ---------------------------------------------------------------------------
__global__ void prep_gates_kernel(const float* __restrict__ qw) {
    int t = threadIdx.x;
    if (t < N_LAYERS * N_QUBITS) {
        float phi = qw[t * 3 + 0];
        float theta = qw[t * 3 + 1];
        float omega = qw[t * 3 + 2];
        float c = cosf(0.5f * theta);
        float s = sinf(0.5f * theta);
        float apo = 0.5f * (phi + omega);
        float apm = 0.5f * (phi - omega);
        float spo, cpo, spm, cpm;
        sincosf(apo, &spo, &cpo);
        sincosf(apm, &spm, &cpm);
        g_U[t][0] = make_float4(cpo * c, -spo * c, -cpm * s, -spm * s);
        g_U[t][1] = make_float4(cpm * s, -spm * s, cpo * c, spo * c);
    }
}

// ---------------------------------------------------------------------------
// K1: tensor-core GEMM (3xTF32) : g_h = relu(x @ W_pre^T + b_pre)
// A = x [4096, 512] row-major, B = W_pre [1024, 512] row-major (K contiguous)
// -> mma row.col with both operands K-contiguous. 128x128x32 block tiles,
// 8 warps, 64x32 warp tiles, fp32 accumulate, hi*hi + hi*lo + lo*hi.
// ---------------------------------------------------------------------------
#define GBM 128
#define GBN 128
#define GBK 32
#define APAD 36   // 36 floats per row -> conflict-free frag loads, 16B aligned

__device__ __forceinline__ void split_tf32(float x, uint32_t& hi, uint32_t& lo) {
    uint32_t h;
    asm("cvt.rna.tf32.f32 %0, %1;" : "=r"(h) : "f"(x));
    hi = h;
    lo = __float_as_uint(x - __uint_as_float(h));
}

__device__ __forceinline__ void mma_tf32(float* c, const uint32_t* a, const uint32_t* b) {
    asm volatile(
        "mma.sync.aligned.m16n8k8.row.col.f32.tf32.tf32.f32 "
        "{%0,%1,%2,%3}, {%4,%5,%6,%7}, {%8,%9}, {%0,%1,%2,%3};\n"
        : "+f"(c[0]), "+f"(c[1]), "+f"(c[2]), "+f"(c[3])
        : "r"(a[0]), "r"(a[1]), "r"(a[2]), "r"(a[3]), "r"(b[0]), "r"(b[1]));
}

__global__ __launch_bounds__(256) void gemm_tc_kernel(
    const float* __restrict__ A, const float* __restrict__ B,
    const float* __restrict__ bias) {
    __shared__ float As[GBM][APAD];
    __shared__ float Bs[GBN][APAD];

    int tid = threadIdx.x;
    int lane = tid & 31;
    int w = tid >> 5;
    int wm = w >> 2;     // 0..1 -> 64-row slab
    int wn = w & 3;      // 0..3 -> 32-col slab
    int gr = lane >> 2;  // 0..7
    int gc = lane & 3;   // 0..3

    int bm = blockIdx.y * GBM;
    int bn = blockIdx.x * GBN;

    float acc[4][4][4];  // [mi][ni][c0..c3]
#pragma unroll
    for (int mi = 0; mi < 4; mi++)
#pragma unroll
        for (int ni = 0; ni < 4; ni++)
#pragma unroll
            for (int q = 0; q < 4; q++) acc[mi][ni][q] = 0.f;

    for (int k0 = 0; k0 < IN_F; k0 += GBK) {
        __syncthreads();
#pragma unroll
        for (int i = 0; i < 4; i++) {
            int idx = tid + 256 * i;        // 0..1023 float4 slots
            int row = idx >> 3;             // 0..127
            int col = (idx & 7) << 2;       // 0..28
            float4 va = *(const float4*)(A + (size_t)(bm + row) * IN_F + k0 + col);
            *(float4*)&As[row][col] = va;
            float4 vb = *(const float4*)(B + (size_t)(bn + row) * IN_F + k0 + col);
            *(float4*)&Bs[row][col] = vb;
        }
        __syncthreads();

#pragma unroll
        for (int k8 = 0; k8 < GBK / 8; k8++) {
            int kb = k8 * 8;
            uint32_t aH[4][4], aL[4][4];
#pragma unroll
            for (int mi = 0; mi < 4; mi++) {
                int rb = wm * 64 + mi * 16;
                split_tf32(As[rb + gr][kb + gc],         aH[mi][0], aL[mi][0]);
                split_tf32(As[rb + 8 + gr][kb + gc],     aH[mi][1], aL[mi][1]);
                split_tf32(As[rb + gr][kb + gc + 4],     aH[mi][2], aL[mi][2]);
                split_tf32(As[rb + 8 + gr][kb + gc + 4], aH[mi][3], aL[mi][3]);
            }
            uint32_t bH[4][2], bL[4][2];
#pragma unroll
            for (int ni = 0; ni < 4; ni++) {
                int nb = wn * 32 + ni * 8;
                split_tf32(Bs[nb + gr][kb + gc],     bH[ni][0], bL[ni][0]);
                split_tf32(Bs[nb + gr][kb + gc + 4], bH[ni][1], bL[ni][1]);
            }
#pragma unroll
            for (int mi = 0; mi < 4; mi++)
#pragma unroll
                for (int ni = 0; ni < 4; ni++) {
                    mma_tf32(acc[mi][ni], aH[mi], bH[ni]);
                    mma_tf32(acc[mi][ni], aH[mi], bL[ni]);
                    mma_tf32(acc[mi][ni], aL[mi], bH[ni]);
                }
        }
    }

    // Epilogue: bias + relu + store
    float bv[4][2];
#pragma unroll
    for (int ni = 0; ni < 4; ni++) {
        int col0 = bn + wn * 32 + ni * 8 + gc * 2;
        bv[ni][0] = bias[col0];
        bv[ni][1] = bias[col0 + 1];
    }
#pragma unroll
    for (int mi = 0; mi < 4; mi++) {
        int row0 = bm + wm * 64 + mi * 16 + gr;
#pragma unroll
        for (int ni = 0; ni < 4; ni++) {
            int col0 = bn + wn * 32 + ni * 8 + gc * 2;
            float v0 = acc[mi][ni][0] + bv[ni][0];
            float v1 = acc[mi][ni][1] + bv[ni][1];
            float v2 = acc[mi][ni][2] + bv[ni][0];
            float v3 = acc[mi][ni][3] + bv[ni][1];
            v0 = v0 > 0.f ? v0 : 0.f;
            v1 = v1 > 0.f ? v1 : 0.f;
            v2 = v2 > 0.f ? v2 : 0.f;
            v3 = v3 > 0.f ? v3 : 0.f;
            *(float2*)&g_h[(size_t)row0 * DIM + col0] = make_float2(v0, v1);
            *(float2*)&g_h[(size_t)(row0 + 8) * DIM + col0] = make_float2(v2, v3);
        }
    }
}

// ---------------------------------------------------------------------------
// K2: per-row statevector simulation + expvals + post linear (unchanged)
// ---------------------------------------------------------------------------
__global__ __launch_bounds__(256) void quantum_kernel(
    const float* __restrict__ W_post, const float* __restrict__ b_post,
    float* __restrict__ out) {
    __shared__ float sre[DIM];
    __shared__ float sim[DIM];
    __shared__ float red[8];
    __shared__ float zred[8][N_QUBITS];
    __shared__ float zfin[N_QUBITS];

    int b = blockIdx.x;
    int tid = threadIdx.x;
    int lane = tid & 31;
    int warp = tid >> 5;

    const float* hrow = g_h + (size_t)b * DIM;

    float n2 = 0.f;
#pragma unroll
    for (int it = 0; it < DIM / 256; it++) {
        int i = tid + it * 256;
        float v = hrow[i];
        sre[i] = v;
        sim[i] = 0.f;
        n2 += v * v;
    }
#pragma unroll
    for (int o = 16; o; o >>= 1) n2 += __shfl_xor_sync(0xffffffffu, n2, o);
    if (lane == 0) red[warp] = n2;

    for (int l = 0; l < N_LAYERS; l++) {
        for (int w = 0; w < N_QUBITS; w++) {
            float4 u0 = g_U[l * N_QUBITS + w][0];
            float4 u1 = g_U[l * N_QUBITS + w][1];
            int bb = 9 - w;
            int lowmask = (1 << bb) - 1;
            __syncthreads();
#pragma unroll
            for (int pp = 0; pp < 2; pp++) {
                int p = tid + pp * 256;
                int i0 = ((p >> bb) << (bb + 1)) | (p & lowmask);
                int i1 = i0 | (1 << bb);
                float ar = sre[i0], ai = sim[i0];
                float br = sre[i1], bi = sim[i1];
                float n0r = u0.x * ar - u0.y * ai + u0.z * br - u0.w * bi;
                float n0i = u0.x * ai + u0.y * ar + u0.z * bi + u0.w * br;
                float n1r = u1.x * ar - u1.y * ai + u1.z * br - u1.w * bi;
                float n1i = u1.x * ai + u1.y * ar + u1.z * bi + u1.w * br;
                sre[i0] = n0r; sim[i0] = n0i;
                sre[i1] = n1r; sim[i1] = n1i;
            }
        }
        int r = (l % (N_QUBITS - 1)) + 1;
        for (int w = 0; w < N_QUBITS; w++) {
            int c = w;
            int t = (w + r) % N_QUBITS;
            int cb = 9 - c, tb = 9 - t;
            int b1 = cb < tb ? cb : tb;
            int b2 = cb < tb ? tb : cb;
            __syncthreads();
            int q = tid;
            int low = q & ((1 << b1) - 1);
            int mid = (q >> b1) & ((1 << (b2 - 1 - b1)) - 1);
            int high = q >> (b2 - 1);
            int i0 = (high << (b2 + 1)) | (mid << (b1 + 1)) | low | (1 << cb);
            int i1 = i0 | (1 << tb);
            float t0r = sre[i0], t0i = sim[i0];
            float t1r = sre[i1], t1i = sim[i1];
            sre[i0] = t1r; sim[i0] = t1i;
            sre[i1] = t0r; sim[i1] = t0i;
        }
    }

    __syncthreads();

    float zl[N_QUBITS];
#pragma unroll
    for (int i = 0; i < N_QUBITS; i++) zl[i] = 0.f;
#pragma unroll
    for (int e = 0; e < 4; e++) {
        int s = tid * 4 + e;
        float p = sre[s] * sre[s] + sim[s] * sim[s];
#pragma unroll
        for (int i = 0; i < N_QUBITS; i++)
            zl[i] += ((s >> (9 - i)) & 1) ? -p : p;
    }
#pragma unroll
    for (int i = 0; i < N_QUBITS; i++) {
#pragma unroll
        for (int o = 16; o; o >>= 1)
            zl[i] += __shfl_xor_sync(0xffffffffu, zl[i], o);
    }
    if (lane == 0) {
#pragma unroll
        for (int i = 0; i < N_QUBITS; i++) zred[warp][i] = zl[i];
    }
    __syncthreads();

    if (tid < N_QUBITS) {
        float norm2 = 0.f;
#pragma unroll
        for (int w = 0; w < 8; w++) norm2 += red[w];
        float s = 0.f;
#pragma unroll
        for (int w = 0; w < 8; w++) s += zred[w][tid];
        zfin[tid] = s / norm2;
    }
    __syncthreads();

    if (tid < OUT_F) {
        float acc = b_post[tid];
#pragma unroll
        for (int i = 0; i < N_QUBITS; i++)
            acc += zfin[i] * W_post[tid * N_QUBITS + i];
        out[(size_t)b * OUT_F + tid] = acc;
    }
}

// ---------------------------------------------------------------------------
extern "C" void kernel_launch(void* const* d_in, const int* in_sizes, int n_in,
                              void* d_out, int out_size) {
    const float* x      = (const float*)d_in[0];
    const float* W_pre  = (const float*)d_in[1];
    const float* b_pre  = (const float*)d_in[2];
    const float* qw     = (const float*)d_in[3];
    const float* W_post = (const float*)d_in[4];
    const float* b_post = (const float*)d_in[5];
    float* out = (float*)d_out;

    prep_gates_kernel<<<1, 64>>>(qw);

    dim3 g1(DIM / GBN, BATCH / GBM);
    gemm_tc_kernel<<<g1, 256>>>(x, W_pre, b_pre);

    quantum_kernel<<<BATCH, 256>>>(W_post, b_post, out);
}

// round 3
// speedup vs baseline: 2.0128x; 1.8780x over previous
#include <cuda_runtime.h>
#include <cuda_bf16.h>
#include <cstdint>

#define N_QUBITS 10
#define DIM 1024
#define IN_F 512
#define OUT_F 64
#define BATCH 4096
#define N_LAYERS 4

// Scratch: h = relu(x @ W_pre^T) [BATCH, DIM]
__device__ float g_h[BATCH * DIM];
// Precomputed Rot matrices: [L*Q][2] float4 = {U00r,U00i,U01r,U01i},{U10r,U10i,U11r,U11i}
__device__ float4 g_U[N_LAYERS * N_QUBITS][2];

// ---------------------------------------------------------------------------
// K0: build 2x2 complex Rot matrices
// ---------------------------------------------------------------------------
__global__ void prep_gates_kernel(const float* __restrict__ qw) {
    int t = threadIdx.x;
    if (t < N_LAYERS * N_QUBITS) {
        float phi = qw[t * 3 + 0];
        float theta = qw[t * 3 + 1];
        float omega = qw[t * 3 + 2];
        float c = cosf(0.5f * theta);
        float s = sinf(0.5f * theta);
        float apo = 0.5f * (phi + omega);
        float apm = 0.5f * (phi - omega);
        float spo, cpo, spm, cpm;
        sincosf(apo, &spo, &cpo);
        sincosf(apm, &spm, &cpm);
        g_U[t][0] = make_float4(cpo * c, -spo * c, -cpm * s, -spm * s);
        g_U[t][1] = make_float4(cpm * s, -spm * s, cpo * c, spo * c);
    }
}

// ---------------------------------------------------------------------------
// K1: tensor-core GEMM (3xTF32): g_h = relu(x @ W_pre^T + b_pre)  (unchanged)
// ---------------------------------------------------------------------------
#define GBM 128
#define GBN 128
#define GBK 32
#define APAD 36

__device__ __forceinline__ void split_tf32(float x, uint32_t& hi, uint32_t& lo) {
    uint32_t h;
    asm("cvt.rna.tf32.f32 %0, %1;" : "=r"(h) : "f"(x));
    hi = h;
    lo = __float_as_uint(x - __uint_as_float(h));
}

__device__ __forceinline__ void mma_tf32(float* c, const uint32_t* a, const uint32_t* b) {
    asm volatile(
        "mma.sync.aligned.m16n8k8.row.col.f32.tf32.tf32.f32 "
        "{%0,%1,%2,%3}, {%4,%5,%6,%7}, {%8,%9}, {%0,%1,%2,%3};\n"
        : "+f"(c[0]), "+f"(c[1]), "+f"(c[2]), "+f"(c[3])
        : "r"(a[0]), "r"(a[1]), "r"(a[2]), "r"(a[3]), "r"(b[0]), "r"(b[1]));
}

__global__ __launch_bounds__(256) void gemm_tc_kernel(
    const float* __restrict__ A, const float* __restrict__ B,
    const float* __restrict__ bias) {
    __shared__ float As[GBM][APAD];
    __shared__ float Bs[GBN][APAD];

    int tid = threadIdx.x;
    int lane = tid & 31;
    int w = tid >> 5;
    int wm = w >> 2;
    int wn = w & 3;
    int gr = lane >> 2;
    int gc = lane & 3;

    int bm = blockIdx.y * GBM;
    int bn = blockIdx.x * GBN;

    float acc[4][4][4];
#pragma unroll
    for (int mi = 0; mi < 4; mi++)
#pragma unroll
        for (int ni = 0; ni < 4; ni++)
#pragma unroll
            for (int q = 0; q < 4; q++) acc[mi][ni][q] = 0.f;

    for (int k0 = 0; k0 < IN_F; k0 += GBK) {
        __syncthreads();
#pragma unroll
        for (int i = 0; i < 4; i++) {
            int idx = tid + 256 * i;
            int row = idx >> 3;
            int col = (idx & 7) << 2;
            float4 va = *(const float4*)(A + (size_t)(bm + row) * IN_F + k0 + col);
            *(float4*)&As[row][col] = va;
            float4 vb = *(const float4*)(B + (size_t)(bn + row) * IN_F + k0 + col);
            *(float4*)&Bs[row][col] = vb;
        }
        __syncthreads();

#pragma unroll
        for (int k8 = 0; k8 < GBK / 8; k8++) {
            int kb = k8 * 8;
            uint32_t aH[4][4], aL[4][4];
#pragma unroll
            for (int mi = 0; mi < 4; mi++) {
                int rb = wm * 64 + mi * 16;
                split_tf32(As[rb + gr][kb + gc],         aH[mi][0], aL[mi][0]);
                split_tf32(As[rb + 8 + gr][kb + gc],     aH[mi][1], aL[mi][1]);
                split_tf32(As[rb + gr][kb + gc + 4],     aH[mi][2], aL[mi][2]);
                split_tf32(As[rb + 8 + gr][kb + gc + 4], aH[mi][3], aL[mi][3]);
            }
            uint32_t bH[4][2], bL[4][2];
#pragma unroll
            for (int ni = 0; ni < 4; ni++) {
                int nb = wn * 32 + ni * 8;
                split_tf32(Bs[nb + gr][kb + gc],     bH[ni][0], bL[ni][0]);
                split_tf32(Bs[nb + gr][kb + gc + 4], bH[ni][1], bL[ni][1]);
            }
#pragma unroll
            for (int mi = 0; mi < 4; mi++)
#pragma unroll
                for (int ni = 0; ni < 4; ni++) {
                    mma_tf32(acc[mi][ni], aH[mi], bH[ni]);
                    mma_tf32(acc[mi][ni], aH[mi], bL[ni]);
                    mma_tf32(acc[mi][ni], aL[mi], bH[ni]);
                }
        }
    }

    float bv[4][2];
#pragma unroll
    for (int ni = 0; ni < 4; ni++) {
        int col0 = bn + wn * 32 + ni * 8 + gc * 2;
        bv[ni][0] = bias[col0];
        bv[ni][1] = bias[col0 + 1];
    }
#pragma unroll
    for (int mi = 0; mi < 4; mi++) {
        int row0 = bm + wm * 64 + mi * 16 + gr;
#pragma unroll
        for (int ni = 0; ni < 4; ni++) {
            int col0 = bn + wn * 32 + ni * 8 + gc * 2;
            float v0 = acc[mi][ni][0] + bv[ni][0];
            float v1 = acc[mi][ni][1] + bv[ni][1];
            float v2 = acc[mi][ni][2] + bv[ni][0];
            float v3 = acc[mi][ni][3] + bv[ni][1];
            v0 = v0 > 0.f ? v0 : 0.f;
            v1 = v1 > 0.f ? v1 : 0.f;
            v2 = v2 > 0.f ? v2 : 0.f;
            v3 = v3 > 0.f ? v3 : 0.f;
            *(float2*)&g_h[(size_t)row0 * DIM + col0] = make_float2(v0, v1);
            *(float2*)&g_h[(size_t)(row0 + 8) * DIM + col0] = make_float2(v2, v3);
        }
    }
}

// ---------------------------------------------------------------------------
// K2: warp-per-row register-resident statevector.
// Amplitude index s (10 bits): lane = s>>5 (bits 9..5), j = s&31 (bits 4..0).
// Wire w acts on bit bb = 9-w.  bb<5 -> register-local gate; bb>=5 -> lane
// (shuffle) gate. CNOT structure is compile-time -> local-local CNOTs are
// register renames (free), others are shfl exchanges / predicated swaps.
// No shared memory, no __syncthreads anywhere.
// ---------------------------------------------------------------------------

template<int BB>
__device__ __forceinline__ void gate_on_bit(float* re, float* im,
                                            const float4 u0, const float4 u1,
                                            int lane) {
    if constexpr (BB < 5) {
#pragma unroll
        for (int p = 0; p < 16; p++) {
            int i0 = ((p >> BB) << (BB + 1)) | (p & ((1 << BB) - 1));
            int i1 = i0 | (1 << BB);
            float ar = re[i0], ai = im[i0], br = re[i1], bi = im[i1];
            re[i0] = u0.x * ar - u0.y * ai + u0.z * br - u0.w * bi;
            im[i0] = u0.x * ai + u0.y * ar + u0.z * bi + u0.w * br;
            re[i1] = u1.x * ar - u1.y * ai + u1.z * br - u1.w * bi;
            im[i1] = u1.x * ai + u1.y * ar + u1.z * bi + u1.w * br;
        }
    } else {
        constexpr int LB = BB - 5;
        bool hi = (lane >> LB) & 1;
        // self/other complex coefficients
        float csr = hi ? u1.z : u0.x;
        float csi = hi ? u1.w : u0.y;
        float cor = hi ? u1.x : u0.z;
        float coi = hi ? u1.y : u0.w;
#pragma unroll
        for (int j = 0; j < 32; j++) {
            float pr = __shfl_xor_sync(0xffffffffu, re[j], 1 << LB);
            float pi = __shfl_xor_sync(0xffffffffu, im[j], 1 << LB);
            float nr = csr * re[j] - csi * im[j] + cor * pr - coi * pi;
            float ni = csr * im[j] + csi * re[j] + cor * pi + coi * pr;
            re[j] = nr;
            im[j] = ni;
        }
    }
}

template<int CB, int TB>
__device__ __forceinline__ void cnot_ct(float* re, float* im, int lane) {
    if constexpr (CB < 5 && TB < 5) {
        // both local: pure register swap (renamed away by ptxas)
#pragma unroll
        for (int j = 0; j < 32; j++) {
            if (((j >> CB) & 1) && !((j >> TB) & 1)) {
                int j1 = j | (1 << TB);
                float t = re[j]; re[j] = re[j1]; re[j1] = t;
                t = im[j]; im[j] = im[j1]; im[j1] = t;
            }
        }
    } else if constexpr (CB < 5 && TB >= 5) {
        // control local, target lane: swap across partner lane for j with CB=1
        constexpr int TLB = TB - 5;
#pragma unroll
        for (int j = 0; j < 32; j++) {
            if ((j >> CB) & 1) {
                re[j] = __shfl_xor_sync(0xffffffffu, re[j], 1 << TLB);
                im[j] = __shfl_xor_sync(0xffffffffu, im[j], 1 << TLB);
            }
        }
    } else if constexpr (CB >= 5 && TB < 5) {
        // control lane, target local: predicated in-thread permutation
        constexpr int CLB = CB - 5;
        bool p = (lane >> CLB) & 1;
#pragma unroll
        for (int j = 0; j < 32; j++) {
            if (!((j >> TB) & 1)) {
                int j1 = j | (1 << TB);
                float a = re[j], b = re[j1];
                re[j] = p ? b : a; re[j1] = p ? a : b;
                a = im[j]; b = im[j1];
                im[j] = p ? b : a; im[j1] = p ? a : b;
            }
        }
    } else {
        // both lane: lanes with control bit set exchange with partner
        constexpr int CLB = CB - 5, TLB = TB - 5;
        bool p = (lane >> CLB) & 1;
#pragma unroll
        for (int j = 0; j < 32; j++) {
            float pr = __shfl_xor_sync(0xffffffffu, re[j], 1 << TLB);
            float pi = __shfl_xor_sync(0xffffffffu, im[j], 1 << TLB);
            re[j] = p ? pr : re[j];
            im[j] = p ? pi : im[j];
        }
    }
}

template<int R, int W>
struct CnotSeq {
    static __device__ __forceinline__ void run(float* re, float* im, int lane) {
        cnot_ct<9 - W, 9 - ((W + R) % N_QUBITS)>(re, im, lane);
        CnotSeq<R, W + 1>::run(re, im, lane);
    }
};
template<int R>
struct CnotSeq<R, N_QUBITS> {
    static __device__ __forceinline__ void run(float*, float*, int) {}
};

__global__ __launch_bounds__(256) void quantum_reg_kernel(
    const float* __restrict__ W_post, const float* __restrict__ b_post,
    float* __restrict__ out) {
    int lane = threadIdx.x & 31;
    int b = blockIdx.x * 8 + (threadIdx.x >> 5);

    float re[32], im[32];
    const float4* hp = (const float4*)(g_h + (size_t)b * DIM + lane * 32);
#pragma unroll
    for (int q = 0; q < 8; q++) {
        float4 v = hp[q];
        re[4 * q + 0] = v.x; re[4 * q + 1] = v.y;
        re[4 * q + 2] = v.z; re[4 * q + 3] = v.w;
        im[4 * q + 0] = 0.f; im[4 * q + 1] = 0.f;
        im[4 * q + 2] = 0.f; im[4 * q + 3] = 0.f;
    }

#pragma unroll 1
    for (int l = 0; l < N_LAYERS; l++) {
        const float4(*U)[2] = &g_U[l * N_QUBITS];
        gate_on_bit<9>(re, im, U[0][0], U[0][1], lane);
        gate_on_bit<8>(re, im, U[1][0], U[1][1], lane);
        gate_on_bit<7>(re, im, U[2][0], U[2][1], lane);
        gate_on_bit<6>(re, im, U[3][0], U[3][1], lane);
        gate_on_bit<5>(re, im, U[4][0], U[4][1], lane);
        gate_on_bit<4>(re, im, U[5][0], U[5][1], lane);
        gate_on_bit<3>(re, im, U[6][0], U[6][1], lane);
        gate_on_bit<2>(re, im, U[7][0], U[7][1], lane);
        gate_on_bit<1>(re, im, U[8][0], U[8][1], lane);
        gate_on_bit<0>(re, im, U[9][0], U[9][1], lane);
        switch (l) {
            case 0:  CnotSeq<1, 0>::run(re, im, lane); break;
            case 1:  CnotSeq<2, 0>::run(re, im, lane); break;
            case 2:  CnotSeq<3, 0>::run(re, im, lane); break;
            default: CnotSeq<4, 0>::run(re, im, lane); break;
        }
    }

    // Expvals: z_w = sum_s sign(bit 9-w of s) * |psi_s|^2 (unnormalized)
    float S = 0.f;
    float zbit[5] = {0.f, 0.f, 0.f, 0.f, 0.f};  // for local bits 0..4
#pragma unroll
    for (int j = 0; j < 32; j++) {
        float p = re[j] * re[j] + im[j] * im[j];
        S += p;
#pragma unroll
        for (int k = 0; k < 5; k++)
            zbit[k] += ((j >> k) & 1) ? -p : p;
    }

    float z[N_QUBITS];
#pragma unroll
    for (int w = 0; w < 5; w++)            // lane wires: bit 9-w -> lane bit 4-w
        z[w] = ((lane >> (4 - w)) & 1) ? -S : S;
#pragma unroll
    for (int w = 5; w < 10; w++)           // local wires: bit 9-w
        z[w] = zbit[9 - w];

    float n2 = S;
#pragma unroll
    for (int o = 16; o; o >>= 1) {
        n2 += __shfl_xor_sync(0xffffffffu, n2, o);
#pragma unroll
        for (int w = 0; w < N_QUBITS; w++)
            z[w] += __shfl_xor_sync(0xffffffffu, z[w], o);
    }
    float inv = 1.f / n2;
#pragma unroll
    for (int w = 0; w < N_QUBITS; w++) z[w] *= inv;

    // Post linear: two outputs per lane
#pragma unroll
    for (int oo = 0; oo < 2; oo++) {
        int o = lane + 32 * oo;
        float acc = b_post[o];
#pragma unroll
        for (int w = 0; w < N_QUBITS; w++)
            acc += z[w] * W_post[o * N_QUBITS + w];
        out[(size_t)b * OUT_F + o] = acc;
    }
}

// ---------------------------------------------------------------------------
extern "C" void kernel_launch(void* const* d_in, const int* in_sizes, int n_in,
                              void* d_out, int out_size) {
    const float* x      = (const float*)d_in[0];
    const float* W_pre  = (const float*)d_in[1];
    const float* b_pre  = (const float*)d_in[2];
    const float* qw     = (const float*)d_in[3];
    const float* W_post = (const float*)d_in[4];
    const float* b_post = (const float*)d_in[5];
    float* out = (float*)d_out;

    prep_gates_kernel<<<1, 64>>>(qw);

    dim3 g1(DIM / GBN, BATCH / GBM);
    gemm_tc_kernel<<<g1, 256>>>(x, W_pre, b_pre);

    quantum_reg_kernel<<<BATCH / 8, 256>>>(W_post, b_post, out);
}

// round 5
// speedup vs baseline: 2.0854x; 1.0361x over previous
#include <cuda_runtime.h>
#include <cuda_bf16.h>
#include <cstdint>

#define N_QUBITS 10
#define DIM 1024
#define IN_F 512
#define OUT_F 64
#define BATCH 4096
#define N_LAYERS 4

typedef unsigned long long u64;

// Scratch: h = relu(x @ W_pre^T) [BATCH, DIM]
__device__ float g_h[BATCH * DIM];
// Packed, lane-duplicated gate coefficients:
// g_Upk[gate][0..7] = dup(U00r),dup(U00i),dup(U01r),dup(U01i),
//                     dup(U10r),dup(U10i),dup(U11r),dup(U11i)
__device__ u64 g_Upk[N_LAYERS * N_QUBITS][8];

// ---------------------------------------------------------------------------
// packed f32x2 helpers
// ---------------------------------------------------------------------------
__device__ __forceinline__ u64 pk2(float lo, float hi) {
    u64 v; asm("mov.b64 %0, {%1, %2};" : "=l"(v) : "f"(lo), "f"(hi)); return v;
}
__device__ __forceinline__ void upk2(u64 v, float& lo, float& hi) {
    asm("mov.b64 {%0, %1}, %2;" : "=f"(lo), "=f"(hi) : "l"(v));
}
__device__ __forceinline__ u64 mul2(u64 a, u64 b) {
    u64 d; asm("mul.rn.f32x2 %0, %1, %2;" : "=l"(d) : "l"(a), "l"(b)); return d;
}
__device__ __forceinline__ u64 fma2(u64 a, u64 b, u64 c) {
    u64 d; asm("fma.rn.f32x2 %0, %1, %2, %3;" : "=l"(d) : "l"(a), "l"(b), "l"(c)); return d;
}
// (r, i) -> (-i, r)   (multiply by +i)
__device__ __forceinline__ u64 swapneg(u64 a) {
    float r, i; upk2(a, r, i);
    return pk2(-i, r);
}

// ---------------------------------------------------------------------------
// K0: build packed Rot matrices.  Rot = RZ(omega) RY(theta) RZ(phi)
// ---------------------------------------------------------------------------
__global__ void prep_gates_kernel(const float* __restrict__ qw) {
    int t = threadIdx.x;
    if (t < N_LAYERS * N_QUBITS) {
        float phi = qw[t * 3 + 0];
        float theta = qw[t * 3 + 1];
        float omega = qw[t * 3 + 2];
        float c = cosf(0.5f * theta);
        float s = sinf(0.5f * theta);
        float apo = 0.5f * (phi + omega);
        float apm = 0.5f * (phi - omega);
        float spo, cpo, spm, cpm;
        sincosf(apo, &spo, &cpo);
        sincosf(apm, &spm, &cpm);
        float u00r = cpo * c, u00i = -spo * c;
        float u01r = -cpm * s, u01i = -spm * s;
        float u10r = cpm * s, u10i = -spm * s;
        float u11r = cpo * c, u11i = spo * c;
        g_Upk[t][0] = pk2(u00r, u00r);
        g_Upk[t][1] = pk2(u00i, u00i);
        g_Upk[t][2] = pk2(u01r, u01r);
        g_Upk[t][3] = pk2(u01i, u01i);
        g_Upk[t][4] = pk2(u10r, u10r);
        g_Upk[t][5] = pk2(u10i, u10i);
        g_Upk[t][6] = pk2(u11r, u11r);
        g_Upk[t][7] = pk2(u11i, u11i);
    }
}

// ---------------------------------------------------------------------------
// K1: tensor-core GEMM (3xTF32): g_h = relu(x @ W_pre^T + b_pre)
// ---------------------------------------------------------------------------
#define GBM 128
#define GBN 128
#define GBK 32
#define APAD 36

__device__ __forceinline__ void split_tf32(float x, uint32_t& hi, uint32_t& lo) {
    uint32_t h;
    asm("cvt.rna.tf32.f32 %0, %1;" : "=r"(h) : "f"(x));
    hi = h;
    lo = __float_as_uint(x - __uint_as_float(h));
}

__device__ __forceinline__ void mma_tf32(float* c, const uint32_t* a, const uint32_t* b) {
    asm volatile(
        "mma.sync.aligned.m16n8k8.row.col.f32.tf32.tf32.f32 "
        "{%0,%1,%2,%3}, {%4,%5,%6,%7}, {%8,%9}, {%0,%1,%2,%3};\n"
        : "+f"(c[0]), "+f"(c[1]), "+f"(c[2]), "+f"(c[3])
        : "r"(a[0]), "r"(a[1]), "r"(a[2]), "r"(a[3]), "r"(b[0]), "r"(b[1]));
}

__global__ __launch_bounds__(256) void gemm_tc_kernel(
    const float* __restrict__ A, const float* __restrict__ B,
    const float* __restrict__ bias) {
    __shared__ float As[GBM][APAD];
    __shared__ float Bs[GBN][APAD];

    int tid = threadIdx.x;
    int lane = tid & 31;
    int w = tid >> 5;
    int wm = w >> 2;
    int wn = w & 3;
    int gr = lane >> 2;
    int gc = lane & 3;

    int bm = blockIdx.y * GBM;
    int bn = blockIdx.x * GBN;

    float acc[4][4][4];
#pragma unroll
    for (int mi = 0; mi < 4; mi++)
#pragma unroll
        for (int ni = 0; ni < 4; ni++)
#pragma unroll
            for (int q = 0; q < 4; q++) acc[mi][ni][q] = 0.f;

    for (int k0 = 0; k0 < IN_F; k0 += GBK) {
        __syncthreads();
#pragma unroll
        for (int i = 0; i < 4; i++) {
            int idx = tid + 256 * i;
            int row = idx >> 3;
            int col = (idx & 7) << 2;
            float4 va = *(const float4*)(A + (size_t)(bm + row) * IN_F + k0 + col);
            *(float4*)&As[row][col] = va;
            float4 vb = *(const float4*)(B + (size_t)(bn + row) * IN_F + k0 + col);
            *(float4*)&Bs[row][col] = vb;
        }
        __syncthreads();

#pragma unroll
        for (int k8 = 0; k8 < GBK / 8; k8++) {
            int kb = k8 * 8;
            uint32_t aH[4][4], aL[4][4];
#pragma unroll
            for (int mi = 0; mi < 4; mi++) {
                int rb = wm * 64 + mi * 16;
                split_tf32(As[rb + gr][kb + gc],         aH[mi][0], aL[mi][0]);
                split_tf32(As[rb + 8 + gr][kb + gc],     aH[mi][1], aL[mi][1]);
                split_tf32(As[rb + gr][kb + gc + 4],     aH[mi][2], aL[mi][2]);
                split_tf32(As[rb + 8 + gr][kb + gc + 4], aH[mi][3], aL[mi][3]);
            }
            uint32_t bH[4][2], bL[4][2];
#pragma unroll
            for (int ni = 0; ni < 4; ni++) {
                int nb = wn * 32 + ni * 8;
                split_tf32(Bs[nb + gr][kb + gc],     bH[ni][0], bL[ni][0]);
                split_tf32(Bs[nb + gr][kb + gc + 4], bH[ni][1], bL[ni][1]);
            }
#pragma unroll
            for (int mi = 0; mi < 4; mi++)
#pragma unroll
                for (int ni = 0; ni < 4; ni++) {
                    mma_tf32(acc[mi][ni], aH[mi], bH[ni]);
                    mma_tf32(acc[mi][ni], aH[mi], bL[ni]);
                    mma_tf32(acc[mi][ni], aL[mi], bH[ni]);
                }
        }
    }

    float bv[4][2];
#pragma unroll
    for (int ni = 0; ni < 4; ni++) {
        int col0 = bn + wn * 32 + ni * 8 + gc * 2;
        bv[ni][0] = bias[col0];
        bv[ni][1] = bias[col0 + 1];
    }
#pragma unroll
    for (int mi = 0; mi < 4; mi++) {
        int row0 = bm + wm * 64 + mi * 16 + gr;
#pragma unroll
        for (int ni = 0; ni < 4; ni++) {
            int col0 = bn + wn * 32 + ni * 8 + gc * 2;
            float v0 = acc[mi][ni][0] + bv[ni][0];
            float v1 = acc[mi][ni][1] + bv[ni][1];
            float v2 = acc[mi][ni][2] + bv[ni][0];
            float v3 = acc[mi][ni][3] + bv[ni][1];
            v0 = v0 > 0.f ? v0 : 0.f;
            v1 = v1 > 0.f ? v1 : 0.f;
            v2 = v2 > 0.f ? v2 : 0.f;
            v3 = v3 > 0.f ? v3 : 0.f;
            *(float2*)&g_h[(size_t)row0 * DIM + col0] = make_float2(v0, v1);
            *(float2*)&g_h[(size_t)(row0 + 8) * DIM + col0] = make_float2(v2, v3);
        }
    }
}

// ---------------------------------------------------------------------------
// K2: warp-per-row register-resident statevector, packed f32x2 math.
// s[j] holds (re, im) as a 64-bit pair.  lane = amp bits 9..5, j = bits 4..0.
// ---------------------------------------------------------------------------

template<int BB>
__device__ __forceinline__ void gate_on_bit(u64* s, const u64* __restrict__ c,
                                            int lane) {
    if constexpr (BB < 5) {
        u64 c0 = c[0], c1 = c[1], c2 = c[2], c3 = c[3];
        u64 c4 = c[4], c5 = c[5], c6 = c[6], c7 = c[7];
#pragma unroll
        for (int p = 0; p < 16; p++) {
            int i0 = ((p >> BB) << (BB + 1)) | (p & ((1 << BB) - 1));
            int i1 = i0 | (1 << BB);
            u64 a = s[i0], b = s[i1];
            u64 at = swapneg(a), bt = swapneg(b);
            u64 n0 = mul2(c0, a);
            n0 = fma2(c1, at, n0);
            n0 = fma2(c2, b, n0);
            n0 = fma2(c3, bt, n0);
            u64 n1 = mul2(c4, a);
            n1 = fma2(c5, at, n1);
            n1 = fma2(c6, b, n1);
            n1 = fma2(c7, bt, n1);
            s[i0] = n0;
            s[i1] = n1;
        }
    } else {
        constexpr int LB = BB - 5;
        bool hi = (lane >> LB) & 1;
        // lo lane holds a0: n = U00*s + U01*p ; hi lane holds a1: n = U11*s + U10*p
        u64 csr = hi ? c[6] : c[0];
        u64 csi = hi ? c[7] : c[1];
        u64 cor = hi ? c[4] : c[2];
        u64 coi = hi ? c[5] : c[3];
#pragma unroll
        for (int j = 0; j < 32; j++) {
            u64 p = __shfl_xor_sync(0xffffffffu, s[j], 1 << LB);
            u64 st = swapneg(s[j]);
            u64 pt = swapneg(p);
            u64 n = mul2(csr, s[j]);
            n = fma2(csi, st, n);
            n = fma2(cor, p, n);
            n = fma2(coi, pt, n);
            s[j] = n;
        }
    }
}

template<int CB, int TB>
__device__ __forceinline__ void cnot_ct(u64* s, int lane) {
    if constexpr (CB < 5 && TB < 5) {
#pragma unroll
        for (int j = 0; j < 32; j++) {
            if (((j >> CB) & 1) && !((j >> TB) & 1)) {
                int j1 = j | (1 << TB);
                u64 t = s[j]; s[j] = s[j1]; s[j1] = t;
            }
        }
    } else if constexpr (CB < 5 && TB >= 5) {
        constexpr int TLB = TB - 5;
#pragma unroll
        for (int j = 0; j < 32; j++) {
            if ((j >> CB) & 1)
                s[j] = __shfl_xor_sync(0xffffffffu, s[j], 1 << TLB);
        }
    } else if constexpr (CB >= 5 && TB < 5) {
        constexpr int CLB = CB - 5;
        bool p = (lane >> CLB) & 1;
#pragma unroll
        for (int j = 0; j < 32; j++) {
            if (!((j >> TB) & 1)) {
                int j1 = j | (1 << TB);
                u64 a = s[j], b = s[j1];
                s[j] = p ? b : a;
                s[j1] = p ? a : b;
            }
        }
    } else {
        constexpr int CLB = CB - 5, TLB = TB - 5;
        bool p = (lane >> CLB) & 1;
#pragma unroll
        for (int j = 0; j < 32; j++) {
            u64 q = __shfl_xor_sync(0xffffffffu, s[j], 1 << TLB);
            s[j] = p ? q : s[j];
        }
    }
}

template<int R, int W>
struct CnotSeq {
    static __device__ __forceinline__ void run(u64* s, int lane) {
        cnot_ct<9 - W, 9 - ((W + R) % N_QUBITS)>(s, lane);
        CnotSeq<R, W + 1>::run(s, lane);
    }
};
template<int R>
struct CnotSeq<R, N_QUBITS> {
    static __device__ __forceinline__ void run(u64*, int) {}
};

__global__ __launch_bounds__(256) void quantum_reg_kernel(
    const float* __restrict__ W_post, const float* __restrict__ b_post,
    float* __restrict__ out) {
    int lane = threadIdx.x & 31;
    int b = blockIdx.x * 8 + (threadIdx.x >> 5);

    u64 s[32];
    const float4* hp = (const float4*)(g_h + (size_t)b * DIM + lane * 32);
#pragma unroll
    for (int q = 0; q < 8; q++) {
        float4 v = hp[q];
        s[4 * q + 0] = pk2(v.x, 0.f);
        s[4 * q + 1] = pk2(v.y, 0.f);
        s[4 * q + 2] = pk2(v.z, 0.f);
        s[4 * q + 3] = pk2(v.w, 0.f);
    }

#pragma unroll 1
    for (int l = 0; l < N_LAYERS; l++) {
        const u64* U = &g_Upk[l * N_QUBITS][0];
        gate_on_bit<9>(s, U + 0 * 8, lane);
        gate_on_bit<8>(s, U + 1 * 8, lane);
        gate_on_bit<7>(s, U + 2 * 8, lane);
        gate_on_bit<6>(s, U + 3 * 8, lane);
        gate_on_bit<5>(s, U + 4 * 8, lane);
        gate_on_bit<4>(s, U + 5 * 8, lane);
        gate_on_bit<3>(s, U + 6 * 8, lane);
        gate_on_bit<2>(s, U + 7 * 8, lane);
        gate_on_bit<1>(s, U + 8 * 8, lane);
        gate_on_bit<0>(s, U + 9 * 8, lane);
        switch (l) {
            case 0:  CnotSeq<1, 0>::run(s, lane); break;
            case 1:  CnotSeq<2, 0>::run(s, lane); break;
            case 2:  CnotSeq<3, 0>::run(s, lane); break;
            default: CnotSeq<4, 0>::run(s, lane); break;
        }
    }

    // Expvals (unnormalized) + norm
    float S = 0.f;
    float zbit[5] = {0.f, 0.f, 0.f, 0.f, 0.f};
#pragma unroll
    for (int j = 0; j < 32; j++) {
        float ar, ai;
        upk2(s[j], ar, ai);
        float p = ar * ar + ai * ai;
        S += p;
#pragma unroll
        for (int k = 0; k < 5; k++)
            zbit[k] += ((j >> k) & 1) ? -p : p;
    }

    float z[N_QUBITS];
#pragma unroll
    for (int w = 0; w < 5; w++)
        z[w] = ((lane >> (4 - w)) & 1) ? -S : S;
#pragma unroll
    for (int w = 5; w < 10; w++)
        z[w] = zbit[9 - w];

    float n2 = S;
#pragma unroll
    for (int o = 16; o; o >>= 1) {
        n2 += __shfl_xor_sync(0xffffffffu, n2, o);
#pragma unroll
        for (int w = 0; w < N_QUBITS; w++)
            z[w] += __shfl_xor_sync(0xffffffffu, z[w], o);
    }
    float inv = 1.f / n2;
#pragma unroll
    for (int w = 0; w < N_QUBITS; w++) z[w] *= inv;

#pragma unroll
    for (int oo = 0; oo < 2; oo++) {
        int o = lane + 32 * oo;
        float acc = b_post[o];
#pragma unroll
        for (int w = 0; w < N_QUBITS; w++)
            acc += z[w] * W_post[o * N_QUBITS + w];
        out[(size_t)b * OUT_F + o] = acc;
    }
}

// ---------------------------------------------------------------------------
extern "C" void kernel_launch(void* const* d_in, const int* in_sizes, int n_in,
                              void* d_out, int out_size) {
    const float* x      = (const float*)d_in[0];
    const float* W_pre  = (const float*)d_in[1];
    const float* b_pre  = (const float*)d_in[2];
    const float* qw     = (const float*)d_in[3];
    const float* W_post = (const float*)d_in[4];
    const float* b_post = (const float*)d_in[5];
    float* out = (float*)d_out;

    prep_gates_kernel<<<1, 64>>>(qw);

    dim3 g1(DIM / GBN, BATCH / GBM);
    gemm_tc_kernel<<<g1, 256>>>(x, W_pre, b_pre);

    quantum_reg_kernel<<<BATCH / 8, 256>>>(W_post, b_post, out);
}

// round 6
// speedup vs baseline: 2.3721x; 1.1375x over previous
#include <cuda_runtime.h>
#include <cuda_bf16.h>
#include <cstdint>

#define N_QUBITS 10
#define DIM 1024
#define IN_F 512
#define OUT_F 64
#define BATCH 4096
#define N_LAYERS 4

typedef unsigned long long u64;

// Scratch: h = relu(x @ W_pre^T) [BATCH, DIM]
__device__ float g_h[BATCH * DIM];
// Merged diagonal phase tables: per layer, per amplitude: {(c,c), (-s,s)}
__device__ ulonglong2 g_E[N_LAYERS * DIM];
// RY coefficients per gate: {(c,c), (s,s), (-s,-s)}
__device__ u64 g_RY[N_LAYERS * N_QUBITS][3];

// ---------------------------------------------------------------------------
// packed f32x2 helpers
// ---------------------------------------------------------------------------
__device__ __forceinline__ u64 pk2(float lo, float hi) {
    u64 v; asm("mov.b64 %0, {%1, %2};" : "=l"(v) : "f"(lo), "f"(hi)); return v;
}
__device__ __forceinline__ void upk2(u64 v, float& lo, float& hi) {
    asm("mov.b64 {%0, %1}, %2;" : "=f"(lo), "=f"(hi) : "l"(v));
}
__device__ __forceinline__ u64 mul2(u64 a, u64 b) {
    u64 d; asm("mul.rn.f32x2 %0, %1, %2;" : "=l"(d) : "l"(a), "l"(b)); return d;
}
__device__ __forceinline__ u64 fma2(u64 a, u64 b, u64 c) {
    u64 d; asm("fma.rn.f32x2 %0, %1, %2, %3;" : "=l"(d) : "l"(a), "l"(b), "l"(c)); return d;
}

// ---------------------------------------------------------------------------
// K0: prep — RY coefficients + merged diagonal tables.
// Layer unitary = Dq(omega) * RY(theta)^{(x10)} * Dp(phi); Dq pushed through
// the CNOT permutation and merged into the next layer's Dp. The final
// leftover diagonal is a pure phase -> dropped (|psi|^2 invariant).
// ---------------------------------------------------------------------------
__global__ void prep_kernel(const float* __restrict__ qw) {
    int s = blockIdx.x * 256 + threadIdx.x;   // 0..1023

    if (s < N_LAYERS * N_QUBITS) {
        float theta = qw[s * 3 + 1];
        float c = cosf(0.5f * theta);
        float sn = sinf(0.5f * theta);
        g_RY[s][0] = pk2(c, c);
        g_RY[s][1] = pk2(sn, sn);
        g_RY[s][2] = pk2(-sn, -sn);
    }

#pragma unroll 1
    for (int l = 0; l < N_LAYERS; l++) {
        float alpha = 0.f;
        // pre phases (RZ(phi)) of layer l at amplitude s
#pragma unroll
        for (int w = 0; w < N_QUBITS; w++) {
            float half = 0.5f * qw[(l * N_QUBITS + w) * 3 + 0];
            alpha += ((s >> (9 - w)) & 1) ? half : -half;
        }
        // post phases (RZ(omega)) of layer l-1, pushed through CNOT layer l-1
        if (l > 0) {
            int lp = l - 1;
            int r = (lp % (N_QUBITS - 1)) + 1;
            int t = s;
            // index map g(s): apply CNOT bit-maps in reverse gate order
            for (int w = N_QUBITS - 1; w >= 0; w--) {
                int cb = 9 - w;
                int tb = 9 - ((w + r) % N_QUBITS);
                t ^= ((t >> cb) & 1) << tb;
            }
#pragma unroll
            for (int w = 0; w < N_QUBITS; w++) {
                float half = 0.5f * qw[(lp * N_QUBITS + w) * 3 + 2];
                alpha += ((t >> (9 - w)) & 1) ? half : -half;
            }
        }
        float sa, ca;
        sincosf(alpha, &sa, &ca);
        g_E[l * DIM + s].x = pk2(ca, ca);
        g_E[l * DIM + s].y = pk2(-sa, sa);
    }
}

// ---------------------------------------------------------------------------
// K1: tensor-core GEMM (3xTF32): g_h = relu(x @ W_pre^T + b_pre)  (unchanged)
// ---------------------------------------------------------------------------
#define GBM 128
#define GBN 128
#define GBK 32
#define APAD 36

__device__ __forceinline__ void split_tf32(float x, uint32_t& hi, uint32_t& lo) {
    uint32_t h;
    asm("cvt.rna.tf32.f32 %0, %1;" : "=r"(h) : "f"(x));
    hi = h;
    lo = __float_as_uint(x - __uint_as_float(h));
}

__device__ __forceinline__ void mma_tf32(float* c, const uint32_t* a, const uint32_t* b) {
    asm volatile(
        "mma.sync.aligned.m16n8k8.row.col.f32.tf32.tf32.f32 "
        "{%0,%1,%2,%3}, {%4,%5,%6,%7}, {%8,%9}, {%0,%1,%2,%3};\n"
        : "+f"(c[0]), "+f"(c[1]), "+f"(c[2]), "+f"(c[3])
        : "r"(a[0]), "r"(a[1]), "r"(a[2]), "r"(a[3]), "r"(b[0]), "r"(b[1]));
}

__global__ __launch_bounds__(256) void gemm_tc_kernel(
    const float* __restrict__ A, const float* __restrict__ B,
    const float* __restrict__ bias) {
    __shared__ float As[GBM][APAD];
    __shared__ float Bs[GBN][APAD];

    int tid = threadIdx.x;
    int lane = tid & 31;
    int w = tid >> 5;
    int wm = w >> 2;
    int wn = w & 3;
    int gr = lane >> 2;
    int gc = lane & 3;

    int bm = blockIdx.y * GBM;
    int bn = blockIdx.x * GBN;

    float acc[4][4][4];
#pragma unroll
    for (int mi = 0; mi < 4; mi++)
#pragma unroll
        for (int ni = 0; ni < 4; ni++)
#pragma unroll
            for (int q = 0; q < 4; q++) acc[mi][ni][q] = 0.f;

    for (int k0 = 0; k0 < IN_F; k0 += GBK) {
        __syncthreads();
#pragma unroll
        for (int i = 0; i < 4; i++) {
            int idx = tid + 256 * i;
            int row = idx >> 3;
            int col = (idx & 7) << 2;
            float4 va = *(const float4*)(A + (size_t)(bm + row) * IN_F + k0 + col);
            *(float4*)&As[row][col] = va;
            float4 vb = *(const float4*)(B + (size_t)(bn + row) * IN_F + k0 + col);
            *(float4*)&Bs[row][col] = vb;
        }
        __syncthreads();

#pragma unroll
        for (int k8 = 0; k8 < GBK / 8; k8++) {
            int kb = k8 * 8;
            uint32_t aH[4][4], aL[4][4];
#pragma unroll
            for (int mi = 0; mi < 4; mi++) {
                int rb = wm * 64 + mi * 16;
                split_tf32(As[rb + gr][kb + gc],         aH[mi][0], aL[mi][0]);
                split_tf32(As[rb + 8 + gr][kb + gc],     aH[mi][1], aL[mi][1]);
                split_tf32(As[rb + gr][kb + gc + 4],     aH[mi][2], aL[mi][2]);
                split_tf32(As[rb + 8 + gr][kb + gc + 4], aH[mi][3], aL[mi][3]);
            }
            uint32_t bH[4][2], bL[4][2];
#pragma unroll
            for (int ni = 0; ni < 4; ni++) {
                int nb = wn * 32 + ni * 8;
                split_tf32(Bs[nb + gr][kb + gc],     bH[ni][0], bL[ni][0]);
                split_tf32(Bs[nb + gr][kb + gc + 4], bH[ni][1], bL[ni][1]);
            }
#pragma unroll
            for (int mi = 0; mi < 4; mi++)
#pragma unroll
                for (int ni = 0; ni < 4; ni++) {
                    mma_tf32(acc[mi][ni], aH[mi], bH[ni]);
                    mma_tf32(acc[mi][ni], aH[mi], bL[ni]);
                    mma_tf32(acc[mi][ni], aL[mi], bH[ni]);
                }
        }
    }

    float bv[4][2];
#pragma unroll
    for (int ni = 0; ni < 4; ni++) {
        int col0 = bn + wn * 32 + ni * 8 + gc * 2;
        bv[ni][0] = bias[col0];
        bv[ni][1] = bias[col0 + 1];
    }
#pragma unroll
    for (int mi = 0; mi < 4; mi++) {
        int row0 = bm + wm * 64 + mi * 16 + gr;
#pragma unroll
        for (int ni = 0; ni < 4; ni++) {
            int col0 = bn + wn * 32 + ni * 8 + gc * 2;
            float v0 = acc[mi][ni][0] + bv[ni][0];
            float v1 = acc[mi][ni][1] + bv[ni][1];
            float v2 = acc[mi][ni][2] + bv[ni][0];
            float v3 = acc[mi][ni][3] + bv[ni][1];
            v0 = v0 > 0.f ? v0 : 0.f;
            v1 = v1 > 0.f ? v1 : 0.f;
            v2 = v2 > 0.f ? v2 : 0.f;
            v3 = v3 > 0.f ? v3 : 0.f;
            *(float2*)&g_h[(size_t)row0 * DIM + col0] = make_float2(v0, v1);
            *(float2*)&g_h[(size_t)(row0 + 8) * DIM + col0] = make_float2(v2, v3);
        }
    }
}

// ---------------------------------------------------------------------------
// K2: warp-per-row register statevector, RZ-merged-diagonal + real-RY form.
// NEW layout: amp index s -> lane = s & 31 (bits 0..4), j = s >> 5 (bits 5..9)
// (fully coalesced loads). Wire w acts on bit P = 9-w:
//   P >= 5 -> register-local (j bit P-5); P < 5 -> lane (shfl mask 1<<P).
// ---------------------------------------------------------------------------

__device__ __forceinline__ u64 swap_halves(u64 v) {
    float lo, hi; upk2(v, lo, hi);
    return pk2(hi, lo);
}

__device__ __forceinline__ void apply_diag(u64* s, const ulonglong2* __restrict__ tab,
                                           int lane) {
#pragma unroll
    for (int j = 0; j < 32; j++) {
        ulonglong2 e = tab[j * 32 + lane];   // e.x = (c,c), e.y = (-sn, sn)
        u64 sw = swap_halves(s[j]);
        s[j] = fma2(e.y, sw, mul2(e.x, s[j]));
    }
}

template<int JB>
__device__ __forceinline__ void ry_local(u64* s, u64 c2, u64 sp, u64 sn) {
#pragma unroll
    for (int p = 0; p < 16; p++) {
        int i0 = ((p >> JB) << (JB + 1)) | (p & ((1 << JB) - 1));
        int i1 = i0 | (1 << JB);
        u64 a = s[i0], b = s[i1];
        s[i0] = fma2(sn, b, mul2(c2, a));   // c*a - s*b
        s[i1] = fma2(sp, a, mul2(c2, b));   // s*a + c*b
    }
}

template<int LB>
__device__ __forceinline__ void ry_lane(u64* s, u64 c2, u64 sp, u64 sn, int lane) {
    bool hi = (lane >> LB) & 1;
    u64 co = hi ? sp : sn;   // bit=0 half: c*a - s*partner ; bit=1: c*b + s*partner
#pragma unroll
    for (int j = 0; j < 32; j++) {
        u64 p = __shfl_xor_sync(0xffffffffu, s[j], 1 << LB);
        s[j] = fma2(co, p, mul2(c2, s[j]));
    }
}

template<int P>
__device__ __forceinline__ void ry_gate(u64* s, u64 c2, u64 sp, u64 sn, int lane) {
    if constexpr (P >= 5) ry_local<P - 5>(s, c2, sp, sn);
    else ry_lane<P>(s, c2, sp, sn, lane);
}

template<int CB, int TB>
__device__ __forceinline__ void cnot_ct(u64* s, int lane) {
    if constexpr (CB >= 5 && TB >= 5) {
        constexpr int C = CB - 5, T = TB - 5;
#pragma unroll
        for (int j = 0; j < 32; j++) {
            if (((j >> C) & 1) && !((j >> T) & 1)) {
                int j1 = j | (1 << T);
                u64 t = s[j]; s[j] = s[j1]; s[j1] = t;
            }
        }
    } else if constexpr (CB >= 5 && TB < 5) {
        constexpr int C = CB - 5;
#pragma unroll
        for (int j = 0; j < 32; j++) {
            if ((j >> C) & 1)
                s[j] = __shfl_xor_sync(0xffffffffu, s[j], 1 << TB);
        }
    } else if constexpr (CB < 5 && TB >= 5) {
        constexpr int T = TB - 5;
        bool p = (lane >> CB) & 1;
#pragma unroll
        for (int j = 0; j < 32; j++) {
            if (!((j >> T) & 1)) {
                int j1 = j | (1 << T);
                u64 a = s[j], b = s[j1];
                s[j] = p ? b : a;
                s[j1] = p ? a : b;
            }
        }
    } else {
        bool p = (lane >> CB) & 1;
#pragma unroll
        for (int j = 0; j < 32; j++) {
            u64 q = __shfl_xor_sync(0xffffffffu, s[j], 1 << TB);
            s[j] = p ? q : s[j];
        }
    }
}

template<int R, int W>
struct CnotSeq {
    static __device__ __forceinline__ void run(u64* s, int lane) {
        cnot_ct<9 - W, 9 - ((W + R) % N_QUBITS)>(s, lane);
        CnotSeq<R, W + 1>::run(s, lane);
    }
};
template<int R>
struct CnotSeq<R, N_QUBITS> {
    static __device__ __forceinline__ void run(u64*, int) {}
};

__global__ __launch_bounds__(256) void quantum_reg_kernel(
    const float* __restrict__ W_post, const float* __restrict__ b_post,
    float* __restrict__ out) {
    int lane = threadIdx.x & 31;
    int b = blockIdx.x * 8 + (threadIdx.x >> 5);

    u64 s[32];
    const float* hrow = g_h + (size_t)b * DIM;
#pragma unroll
    for (int j = 0; j < 32; j++) {
        float v = hrow[j * 32 + lane];   // coalesced
        s[j] = pk2(v, 0.f);
    }

#pragma unroll 1
    for (int l = 0; l < N_LAYERS; l++) {
        apply_diag(s, g_E + l * DIM, lane);
        const u64(*R)[3] = (const u64(*)[3]) & g_RY[l * N_QUBITS][0];
        ry_gate<9>(s, R[0][0], R[0][1], R[0][2], lane);   // wire 0
        ry_gate<8>(s, R[1][0], R[1][1], R[1][2], lane);
        ry_gate<7>(s, R[2][0], R[2][1], R[2][2], lane);
        ry_gate<6>(s, R[3][0], R[3][1], R[3][2], lane);
        ry_gate<5>(s, R[4][0], R[4][1], R[4][2], lane);
        ry_gate<4>(s, R[5][0], R[5][1], R[5][2], lane);
        ry_gate<3>(s, R[6][0], R[6][1], R[6][2], lane);
        ry_gate<2>(s, R[7][0], R[7][1], R[7][2], lane);
        ry_gate<1>(s, R[8][0], R[8][1], R[8][2], lane);
        ry_gate<0>(s, R[9][0], R[9][1], R[9][2], lane);   // wire 9
        switch (l) {
            case 0:  CnotSeq<1, 0>::run(s, lane); break;
            case 1:  CnotSeq<2, 0>::run(s, lane); break;
            case 2:  CnotSeq<3, 0>::run(s, lane); break;
            default: CnotSeq<4, 0>::run(s, lane); break;
        }
    }
    // (final merged post-diagonal is a pure per-amplitude phase: dropped,
    //  since only |amplitude|^2 enters the measurement)

    // Expvals (unnormalized) + norm.
    // j bits 0..4 = amp bits 5..9 = wires 4..0 ; lane bits 0..4 = wires 9..5.
    float S = 0.f;
    float zbit[5] = {0.f, 0.f, 0.f, 0.f, 0.f};
#pragma unroll
    for (int j = 0; j < 32; j++) {
        float ar, ai;
        upk2(s[j], ar, ai);
        float p = ar * ar + ai * ai;
        S += p;
#pragma unroll
        for (int k = 0; k < 5; k++)
            zbit[k] += ((j >> k) & 1) ? -p : p;
    }

    float z[N_QUBITS];
#pragma unroll
    for (int w = 0; w < 5; w++)            // wires 0..4: j bit 4-w
        z[w] = zbit[4 - w];
#pragma unroll
    for (int w = 5; w < 10; w++)           // wires 5..9: lane bit 9-w
        z[w] = ((lane >> (9 - w)) & 1) ? -S : S;

    float n2 = S;
#pragma unroll
    for (int o = 16; o; o >>= 1) {
        n2 += __shfl_xor_sync(0xffffffffu, n2, o);
#pragma unroll
        for (int w = 0; w < N_QUBITS; w++)
            z[w] += __shfl_xor_sync(0xffffffffu, z[w], o);
    }
    float inv = 1.f / n2;
#pragma unroll
    for (int w = 0; w < N_QUBITS; w++) z[w] *= inv;

#pragma unroll
    for (int oo = 0; oo < 2; oo++) {
        int o = lane + 32 * oo;
        float acc = b_post[o];
#pragma unroll
        for (int w = 0; w < N_QUBITS; w++)
            acc += z[w] * W_post[o * N_QUBITS + w];
        out[(size_t)b * OUT_F + o] = acc;
    }
}

// ---------------------------------------------------------------------------
extern "C" void kernel_launch(void* const* d_in, const int* in_sizes, int n_in,
                              void* d_out, int out_size) {
    const float* x      = (const float*)d_in[0];
    const float* W_pre  = (const float*)d_in[1];
    const float* b_pre  = (const float*)d_in[2];
    const float* qw     = (const float*)d_in[3];
    const float* W_post = (const float*)d_in[4];
    const float* b_post = (const float*)d_in[5];
    float* out = (float*)d_out;

    prep_kernel<<<4, 256>>>(qw);

    dim3 g1(DIM / GBN, BATCH / GBM);
    gemm_tc_kernel<<<g1, 256>>>(x, W_pre, b_pre);

    quantum_reg_kernel<<<BATCH / 8, 256>>>(W_post, b_post, out);
}

// round 7
// speedup vs baseline: 2.6358x; 1.1112x over previous
#include <cuda_runtime.h>
#include <cuda_bf16.h>
#include <cstdint>

#define N_QUBITS 10
#define DIM 1024
#define IN_F 512
#define OUT_F 64
#define BATCH 4096
#define N_LAYERS 4

typedef unsigned long long u64;

// Scratch: h = relu(x @ W_pre^T) [BATCH, DIM]
__device__ float g_h[BATCH * DIM];
// Merged diagonal phase tables: per layer, per amplitude: {(c,c), (-s,s)}
__device__ ulonglong2 g_E[N_LAYERS * DIM];
// RY coefficients per gate: {(c,c), (s,s), (-s,-s)}
__device__ u64 g_RY[N_LAYERS * N_QUBITS][3];
// bf16 split operands for the pre-GEMM
__device__ __nv_bfloat16 g_Ah[BATCH * IN_F];
__device__ __nv_bfloat16 g_Al[BATCH * IN_F];
__device__ __nv_bfloat16 g_Bh[DIM * IN_F];
__device__ __nv_bfloat16 g_Bl[DIM * IN_F];

// ---------------------------------------------------------------------------
// helpers
// ---------------------------------------------------------------------------
__device__ __forceinline__ u64 pk2(float lo, float hi) {
    u64 v; asm("mov.b64 %0, {%1, %2};" : "=l"(v) : "f"(lo), "f"(hi)); return v;
}
__device__ __forceinline__ void upk2(u64 v, float& lo, float& hi) {
    asm("mov.b64 {%0, %1}, %2;" : "=f"(lo), "=f"(hi) : "l"(v));
}
__device__ __forceinline__ u64 mul2(u64 a, u64 b) {
    u64 d; asm("mul.rn.f32x2 %0, %1, %2;" : "=l"(d) : "l"(a), "l"(b)); return d;
}
__device__ __forceinline__ u64 fma2(u64 a, u64 b, u64 c) {
    u64 d; asm("fma.rn.f32x2 %0, %1, %2, %3;" : "=l"(d) : "l"(a), "l"(b), "l"(c)); return d;
}
__device__ __forceinline__ uint32_t smem_u32(const void* p) {
    return (uint32_t)__cvta_generic_to_shared(p);
}
__device__ __forceinline__ void cpa16(uint32_t dst, const void* src) {
    asm volatile("cp.async.ca.shared.global [%0], [%1], 16;\n" :: "r"(dst), "l"(src));
}

// ---------------------------------------------------------------------------
// K0a: gate prep — RY coefficients + merged diagonal tables
// ---------------------------------------------------------------------------
__global__ void prep_kernel(const float* __restrict__ qw) {
    int s = blockIdx.x * 256 + threadIdx.x;   // 0..1023

    if (s < N_LAYERS * N_QUBITS) {
        float theta = qw[s * 3 + 1];
        float c = cosf(0.5f * theta);
        float sn = sinf(0.5f * theta);
        g_RY[s][0] = pk2(c, c);
        g_RY[s][1] = pk2(sn, sn);
        g_RY[s][2] = pk2(-sn, -sn);
    }

#pragma unroll 1
    for (int l = 0; l < N_LAYERS; l++) {
        float alpha = 0.f;
#pragma unroll
        for (int w = 0; w < N_QUBITS; w++) {
            float half = 0.5f * qw[(l * N_QUBITS + w) * 3 + 0];
            alpha += ((s >> (9 - w)) & 1) ? half : -half;
        }
        if (l > 0) {
            int lp = l - 1;
            int r = (lp % (N_QUBITS - 1)) + 1;
            int t = s;
            for (int w = N_QUBITS - 1; w >= 0; w--) {
                int cb = 9 - w;
                int tb = 9 - ((w + r) % N_QUBITS);
                t ^= ((t >> cb) & 1) << tb;
            }
#pragma unroll
            for (int w = 0; w < N_QUBITS; w++) {
                float half = 0.5f * qw[(lp * N_QUBITS + w) * 3 + 2];
                alpha += ((t >> (9 - w)) & 1) ? half : -half;
            }
        }
        float sa, ca;
        sincosf(alpha, &sa, &ca);
        g_E[l * DIM + s].x = pk2(ca, ca);
        g_E[l * DIM + s].y = pk2(-sa, sa);
    }
}

// ---------------------------------------------------------------------------
// K0b: split x and W_pre into bf16 hi/lo
// ---------------------------------------------------------------------------
__global__ void split_kernel(const float* __restrict__ x, const float* __restrict__ w) {
    int i = blockIdx.x * 256 + threadIdx.x;
    const int AQ = (BATCH * IN_F) / 4;
    float4 v;
    __nv_bfloat16 *hd, *ld;
    int base;
    if (i < AQ) {
        v = ((const float4*)x)[i];
        hd = g_Ah; ld = g_Al; base = i * 4;
    } else {
        int j = i - AQ;
        v = ((const float4*)w)[j];
        hd = g_Bh; ld = g_Bl; base = j * 4;
    }
    float vv[4] = {v.x, v.y, v.z, v.w};
#pragma unroll
    for (int q = 0; q < 4; q++) {
        __nv_bfloat16 h = __float2bfloat16(vv[q]);
        hd[base + q] = h;
        ld[base + q] = __float2bfloat16(vv[q] - __bfloat162float(h));
    }
}

// ---------------------------------------------------------------------------
// K1: bf16-split tensor GEMM: g_h = relu(x @ W_pre^T + b_pre)
// 128x128 block tile, BK=16, 2-stage cp.async pipeline, ldmatrix frags.
// acc = Ah*Bh + Ah*Bl + Al*Bh  (ll term dropped, ~2^-16 relative)
// ---------------------------------------------------------------------------
#define SROW 24   // smem row stride in bf16 (16 data + 8 pad) = 48B, conflict-free

__device__ __forceinline__ void mma_bf16(float* c, const uint32_t* a, const uint32_t* b) {
    asm volatile(
        "mma.sync.aligned.m16n8k16.row.col.f32.bf16.bf16.f32 "
        "{%0,%1,%2,%3}, {%4,%5,%6,%7}, {%8,%9}, {%0,%1,%2,%3};\n"
        : "+f"(c[0]), "+f"(c[1]), "+f"(c[2]), "+f"(c[3])
        : "r"(a[0]), "r"(a[1]), "r"(a[2]), "r"(a[3]), "r"(b[0]), "r"(b[1]));
}
#define LDSM4(r0, r1, r2, r3, addr)                                        \
    asm volatile("ldmatrix.sync.aligned.m8n8.x4.shared.b16 {%0,%1,%2,%3}, [%4];" \
                 : "=r"(r0), "=r"(r1), "=r"(r2), "=r"(r3) : "r"(addr))

__global__ __launch_bounds__(256, 2) void gemm_bf16_kernel(const float* __restrict__ bias) {
    // [stage][hi/lo][row][col]
    __shared__ __nv_bfloat16 sA[2][2][128][SROW];
    __shared__ __nv_bfloat16 sB[2][2][128][SROW];

    int tid = threadIdx.x;
    int lane = tid & 31;
    int w = tid >> 5;
    int wm = w >> 2;      // 0..1
    int wn = w & 3;       // 0..3
    int gr = lane >> 2;
    int gc = lane & 3;
    int bm = blockIdx.y * 128;
    int bn = blockIdx.x * 128;

    float acc[4][4][4];
#pragma unroll
    for (int mi = 0; mi < 4; mi++)
#pragma unroll
        for (int ni = 0; ni < 4; ni++)
#pragma unroll
            for (int q = 0; q < 4; q++) acc[mi][ni][q] = 0.f;

    // cp.async mapping: thread handles row r of (A hi|lo) and (B hi|lo)
    int r = tid & 127;
    int half = (tid >> 7) & 1;
    const __nv_bfloat16* gA = (half ? g_Al : g_Ah) + (size_t)(bm + r) * IN_F;
    const __nv_bfloat16* gB = (half ? g_Bl : g_Bh) + (size_t)(bn + r) * IN_F;
    uint32_t dA = smem_u32(&sA[0][half][r][0]);
    uint32_t dB = smem_u32(&sB[0][half][r][0]);
    const uint32_t STG = 2 * 128 * SROW * 2;   // stage stride bytes (12288)

    // ldmatrix lane offsets (bytes, relative to frag base row)
    int arow = ((lane >> 3) & 1) * 8 + (lane & 7);
    int acol = (lane >> 4) * 8;
    uint32_t aoff = (uint32_t)(arow * SROW + acol) * 2;
    int brow = ((lane >> 4) & 1) * 8 + (lane & 7);
    int bcol = ((lane >> 3) & 1) * 8;
    uint32_t boff = (uint32_t)(brow * SROW + bcol) * 2;

    uint32_t sA_base = smem_u32(&sA[0][0][0][0]);
    uint32_t sB_base = smem_u32(&sB[0][0][0][0]);
    const uint32_t HL = 128 * SROW * 2;        // hi->lo stride (6144)

    const int NK = IN_F / 16;   // 32

    // prologue: stage 0
    cpa16(dA, gA);
    cpa16(dA + 16, gA + 8);
    cpa16(dB, gB);
    cpa16(dB + 16, gB + 8);
    asm volatile("cp.async.commit_group;\n");

    for (int k = 0; k < NK; k++) {
        int buf = k & 1;
        asm volatile("cp.async.wait_group 0;\n");
        __syncthreads();
        if (k + 1 < NK) {
            uint32_t so = (uint32_t)((k + 1) & 1) * STG;
            const __nv_bfloat16* pA = gA + (k + 1) * 16;
            const __nv_bfloat16* pB = gB + (k + 1) * 16;
            cpa16(dA + so, pA);
            cpa16(dA + so + 16, pA + 8);
            cpa16(dB + so, pB);
            cpa16(dB + so + 16, pB + 8);
            asm volatile("cp.async.commit_group;\n");
        }

        // B fragments (4 n-frags, hi+lo)
        uint32_t bh[4][2], bl[4][2];
#pragma unroll
        for (int p = 0; p < 2; p++) {
            uint32_t base = sB_base + (uint32_t)buf * STG +
                            (uint32_t)(wn * 32 + p * 16) * (SROW * 2) + boff;
            uint32_t r0, r1, r2, r3;
            LDSM4(r0, r1, r2, r3, base);
            bh[2 * p][0] = r0; bh[2 * p][1] = r1;
            bh[2 * p + 1][0] = r2; bh[2 * p + 1][1] = r3;
            LDSM4(r0, r1, r2, r3, base + HL);
            bl[2 * p][0] = r0; bl[2 * p][1] = r1;
            bl[2 * p + 1][0] = r2; bl[2 * p + 1][1] = r3;
        }

#pragma unroll
        for (int mi = 0; mi < 4; mi++) {
            uint32_t base = sA_base + (uint32_t)buf * STG +
                            (uint32_t)(wm * 64 + mi * 16) * (SROW * 2) + aoff;
            uint32_t ah[4], al[4];
            LDSM4(ah[0], ah[1], ah[2], ah[3], base);
            LDSM4(al[0], al[1], al[2], al[3], base + HL);
#pragma unroll
            for (int ni = 0; ni < 4; ni++) {
                mma_bf16(acc[mi][ni], ah, bh[ni]);
                mma_bf16(acc[mi][ni], ah, bl[ni]);
                mma_bf16(acc[mi][ni], al, bh[ni]);
            }
        }
    }

    // Epilogue: bias + relu + store (c frag: c0 (gr,2gc) c1 (gr,2gc+1) c2/c3 +8 rows)
    float bv[4][2];
#pragma unroll
    for (int ni = 0; ni < 4; ni++) {
        int col0 = bn + wn * 32 + ni * 8 + gc * 2;
        bv[ni][0] = bias[col0];
        bv[ni][1] = bias[col0 + 1];
    }
#pragma unroll
    for (int mi = 0; mi < 4; mi++) {
        int row0 = bm + wm * 64 + mi * 16 + gr;
#pragma unroll
        for (int ni = 0; ni < 4; ni++) {
            int col0 = bn + wn * 32 + ni * 8 + gc * 2;
            float v0 = acc[mi][ni][0] + bv[ni][0];
            float v1 = acc[mi][ni][1] + bv[ni][1];
            float v2 = acc[mi][ni][2] + bv[ni][0];
            float v3 = acc[mi][ni][3] + bv[ni][1];
            v0 = v0 > 0.f ? v0 : 0.f;
            v1 = v1 > 0.f ? v1 : 0.f;
            v2 = v2 > 0.f ? v2 : 0.f;
            v3 = v3 > 0.f ? v3 : 0.f;
            *(float2*)&g_h[(size_t)row0 * DIM + col0] = make_float2(v0, v1);
            *(float2*)&g_h[(size_t)(row0 + 8) * DIM + col0] = make_float2(v2, v3);
        }
    }
}

// ---------------------------------------------------------------------------
// K2: warp-per-row register statevector (unchanged from R6)
// ---------------------------------------------------------------------------
__device__ __forceinline__ u64 swap_halves(u64 v) {
    float lo, hi; upk2(v, lo, hi);
    return pk2(hi, lo);
}

__device__ __forceinline__ void apply_diag(u64* s, const ulonglong2* __restrict__ tab,
                                           int lane) {
#pragma unroll
    for (int j = 0; j < 32; j++) {
        ulonglong2 e = tab[j * 32 + lane];
        u64 sw = swap_halves(s[j]);
        s[j] = fma2(e.y, sw, mul2(e.x, s[j]));
    }
}

template<int JB>
__device__ __forceinline__ void ry_local(u64* s, u64 c2, u64 sp, u64 sn) {
#pragma unroll
    for (int p = 0; p < 16; p++) {
        int i0 = ((p >> JB) << (JB + 1)) | (p & ((1 << JB) - 1));
        int i1 = i0 | (1 << JB);
        u64 a = s[i0], b = s[i1];
        s[i0] = fma2(sn, b, mul2(c2, a));
        s[i1] = fma2(sp, a, mul2(c2, b));
    }
}

template<int LB>
__device__ __forceinline__ void ry_lane(u64* s, u64 c2, u64 sp, u64 sn, int lane) {
    bool hi = (lane >> LB) & 1;
    u64 co = hi ? sp : sn;
#pragma unroll
    for (int j = 0; j < 32; j++) {
        u64 p = __shfl_xor_sync(0xffffffffu, s[j], 1 << LB);
        s[j] = fma2(co, p, mul2(c2, s[j]));
    }
}

template<int P>
__device__ __forceinline__ void ry_gate(u64* s, u64 c2, u64 sp, u64 sn, int lane) {
    if constexpr (P >= 5) ry_local<P - 5>(s, c2, sp, sn);
    else ry_lane<P>(s, c2, sp, sn, lane);
}

template<int CB, int TB>
__device__ __forceinline__ void cnot_ct(u64* s, int lane) {
    if constexpr (CB >= 5 && TB >= 5) {
        constexpr int C = CB - 5, T = TB - 5;
#pragma unroll
        for (int j = 0; j < 32; j++) {
            if (((j >> C) & 1) && !((j >> T) & 1)) {
                int j1 = j | (1 << T);
                u64 t = s[j]; s[j] = s[j1]; s[j1] = t;
            }
        }
    } else if constexpr (CB >= 5 && TB < 5) {
        constexpr int C = CB - 5;
#pragma unroll
        for (int j = 0; j < 32; j++) {
            if ((j >> C) & 1)
                s[j] = __shfl_xor_sync(0xffffffffu, s[j], 1 << TB);
        }
    } else if constexpr (CB < 5 && TB >= 5) {
        constexpr int T = TB - 5;
        bool p = (lane >> CB) & 1;
#pragma unroll
        for (int j = 0; j < 32; j++) {
            if (!((j >> T) & 1)) {
                int j1 = j | (1 << T);
                u64 a = s[j], b = s[j1];
                s[j] = p ? b : a;
                s[j1] = p ? a : b;
            }
        }
    } else {
        bool p = (lane >> CB) & 1;
#pragma unroll
        for (int j = 0; j < 32; j++) {
            u64 q = __shfl_xor_sync(0xffffffffu, s[j], 1 << TB);
            s[j] = p ? q : s[j];
        }
    }
}

template<int R, int W>
struct CnotSeq {
    static __device__ __forceinline__ void run(u64* s, int lane) {
        cnot_ct<9 - W, 9 - ((W + R) % N_QUBITS)>(s, lane);
        CnotSeq<R, W + 1>::run(s, lane);
    }
};
template<int R>
struct CnotSeq<R, N_QUBITS> {
    static __device__ __forceinline__ void run(u64*, int) {}
};

__global__ __launch_bounds__(256) void quantum_reg_kernel(
    const float* __restrict__ W_post, const float* __restrict__ b_post,
    float* __restrict__ out) {
    int lane = threadIdx.x & 31;
    int b = blockIdx.x * 8 + (threadIdx.x >> 5);

    u64 s[32];
    const float* hrow = g_h + (size_t)b * DIM;
#pragma unroll
    for (int j = 0; j < 32; j++) {
        float v = hrow[j * 32 + lane];
        s[j] = pk2(v, 0.f);
    }

#pragma unroll 1
    for (int l = 0; l < N_LAYERS; l++) {
        apply_diag(s, g_E + l * DIM, lane);
        const u64(*R)[3] = (const u64(*)[3]) & g_RY[l * N_QUBITS][0];
        ry_gate<9>(s, R[0][0], R[0][1], R[0][2], lane);
        ry_gate<8>(s, R[1][0], R[1][1], R[1][2], lane);
        ry_gate<7>(s, R[2][0], R[2][1], R[2][2], lane);
        ry_gate<6>(s, R[3][0], R[3][1], R[3][2], lane);
        ry_gate<5>(s, R[4][0], R[4][1], R[4][2], lane);
        ry_gate<4>(s, R[5][0], R[5][1], R[5][2], lane);
        ry_gate<3>(s, R[6][0], R[6][1], R[6][2], lane);
        ry_gate<2>(s, R[7][0], R[7][1], R[7][2], lane);
        ry_gate<1>(s, R[8][0], R[8][1], R[8][2], lane);
        ry_gate<0>(s, R[9][0], R[9][1], R[9][2], lane);
        switch (l) {
            case 0:  CnotSeq<1, 0>::run(s, lane); break;
            case 1:  CnotSeq<2, 0>::run(s, lane); break;
            case 2:  CnotSeq<3, 0>::run(s, lane); break;
            default: CnotSeq<4, 0>::run(s, lane); break;
        }
    }

    float S = 0.f;
    float zbit[5] = {0.f, 0.f, 0.f, 0.f, 0.f};
#pragma unroll
    for (int j = 0; j < 32; j++) {
        float ar, ai;
        upk2(s[j], ar, ai);
        float p = ar * ar + ai * ai;
        S += p;
#pragma unroll
        for (int k = 0; k < 5; k++)
            zbit[k] += ((j >> k) & 1) ? -p : p;
    }

    float z[N_QUBITS];
#pragma unroll
    for (int w = 0; w < 5; w++)
        z[w] = zbit[4 - w];
#pragma unroll
    for (int w = 5; w < 10; w++)
        z[w] = ((lane >> (9 - w)) & 1) ? -S : S;

    float n2 = S;
#pragma unroll
    for (int o = 16; o; o >>= 1) {
        n2 += __shfl_xor_sync(0xffffffffu, n2, o);
#pragma unroll
        for (int w = 0; w < N_QUBITS; w++)
            z[w] += __shfl_xor_sync(0xffffffffu, z[w], o);
    }
    float inv = 1.f / n2;
#pragma unroll
    for (int w = 0; w < N_QUBITS; w++) z[w] *= inv;

#pragma unroll
    for (int oo = 0; oo < 2; oo++) {
        int o = lane + 32 * oo;
        float acc = b_post[o];
#pragma unroll
        for (int w = 0; w < N_QUBITS; w++)
            acc += z[w] * W_post[o * N_QUBITS + w];
        out[(size_t)b * OUT_F + o] = acc;
    }
}

// ---------------------------------------------------------------------------
extern "C" void kernel_launch(void* const* d_in, const int* in_sizes, int n_in,
                              void* d_out, int out_size) {
    const float* x      = (const float*)d_in[0];
    const float* W_pre  = (const float*)d_in[1];
    const float* b_pre  = (const float*)d_in[2];
    const float* qw     = (const float*)d_in[3];
    const float* W_post = (const float*)d_in[4];
    const float* b_post = (const float*)d_in[5];
    float* out = (float*)d_out;

    prep_kernel<<<4, 256>>>(qw);
    split_kernel<<<(BATCH * IN_F + DIM * IN_F) / 4 / 256, 256>>>(x, W_pre);

    dim3 g1(DIM / 128, BATCH / 128);
    gemm_bf16_kernel<<<g1, 256>>>(b_pre);

    quantum_reg_kernel<<<BATCH / 8, 256>>>(W_post, b_post, out);
}